// round 12
// baseline (speedup 1.0000x reference)
#include <cuda_runtime.h>
#include <cstdint>

#define GQ     640
#define NIMG   320
#define NCOIL  12
#define MPTS   102400
#define PI_F   3.14159265358979f
#define BETA_F 13.855101f      // pi * sqrt((6*1.5/2)^2 - 0.8)
#define INV_G  0.0015625f      // 1/640

// Per-boundary bank swizzles (float2 elements).
#define SW1(i) ((i) ^ (((i) >> 4) & 3))          // stage0->1 and stage2->r5 layouts
#define SW2(i) ((i) ^ ((((i) >> 4) & 3) << 2))   // stage1->2 layout

// Scratch (zero-initialized at module load).
__device__ float2 g_gridA[NCOIL * GQ * GQ];                 // [coil][row][col]
__device__ float2 g_gridB[NCOIL * GQ * GQ];                 // [coil][row][col] after col FFT
__device__ __align__(16) float2 g_gridC[GQ * GQ * NCOIL];   // [row][col][coil]
__device__ float  g_scale[NIMG];
__device__ float2 g_tw[GQ];                                 // exp(-2*pi*i*k/640)

__constant__ float c5r[5] = {1.0f, 0.30901699f, -0.80901699f, -0.80901699f, 0.30901699f};
__constant__ float c5i[5] = {0.0f, -0.95105652f, -0.58778525f, 0.58778525f, 0.95105652f};

// ---------------------------------------------------------------------------
// Modified Bessel I0 (Abramowitz & Stegun, ~2e-7 rel error)
// ---------------------------------------------------------------------------
__device__ __forceinline__ float i0f_dev(float x) {
    if (x < 3.75f) {
        float t = x * (1.0f / 3.75f);
        t *= t;
        return 1.0f + t * (3.5156229f + t * (3.0899424f + t * (1.2067492f
             + t * (0.2659732f + t * (0.0360768f + t * 0.0045813f)))));
    } else {
        float t = 3.75f / x;
        float p = 0.39894228f + t * (0.01328592f + t * (0.00225319f + t * (-0.00157565f
                + t * (0.00916281f + t * (-0.02057706f + t * (0.02635537f
                + t * (-0.01647633f + t * 0.00392377f)))))));
        return expf(x) * rsqrtf(x) * p;
    }
}

// Kaiser-Bessel kernel, support |u| <= 3 (J=6)
__device__ __forceinline__ float kbf(float u) {
    float m = fabsf(u) * (1.0f / 3.0f);
    float a = 1.0f - m * m;
    a = a > 0.0f ? a : 0.0f;
    float v = i0f_dev(BETA_F * sqrtf(a)) * (1.0f / 6.0f);
    return (m <= 1.0f) ? v : 0.0f;
}

// ---------------------------------------------------------------------------
// Apodization scale (length 320) + twiddle table (length 640).
// grid = 5 blocks x 128 threads (spread across SMs).
// ---------------------------------------------------------------------------
__global__ void apod_kernel() {
    int n = blockIdx.x * 128 + threadIdx.x;
    if (n < NIMG) {
        float acc = 0.0f;
        #pragma unroll
        for (int j = -6; j <= 6; j++) {
            float kv = kbf((float)j);
            acc += kv * cosf(2.0f * PI_F * (float)j * ((float)n - 160.0f) * (1.0f / 640.0f));
        }
        g_scale[n] = 1.0f / acc;
    }
    if (n < GQ) {
        float sn, cs;
        sincospif(-(float)n * (1.0f / 320.0f), &sn, &cs);   // -2*pi*n/640
        g_tw[n] = make_float2(cs, sn);
    }
}

__device__ __forceinline__ float2 cmul(float2 a, float2 b) {
    return make_float2(a.x * b.x - a.y * b.y, a.x * b.y + a.y * b.x);
}

// ---------------------------------------------------------------------------
// TWO 640-point forward FFTs per call. 640 = 5 * 128; 128 = three composed
// radix-4 Stockham stages + radix-2 (fused into the radix-5 combine).
// Inputs in0/in1: NATURAL-order float2[640] arrays (may alias Wa halves).
// Wa/Wb: work buffers float2[2*640]. Outputs out0/out1: natural order,
// scaled by outScale (global or smem). blockDim.x == 320.
// NOTE: no trailing __syncthreads(); caller adds one if buffers are reused.
// ---------------------------------------------------------------------------
__device__ void fft640_v2(const float2* in0, const float2* in1,
                          float2* Wa, float2* Wb, const float2* tw, int t,
                          float2* out0, float2* out1, float outScale) {
    const int f  = (t >= 160) ? 1 : 0;
    const int lt = t - 160 * f;
    const int n1 = lt >> 5;
    const int u  = lt & 31;
    const float2* in = f ? in1 : in0;
    float2* A = Wa + f * 640;
    float2* B = Wb + f * 640;

    // ---- stage 0 (s=1): natural in -> B (SW1) ----
    {
        float2 x0 = in[5 * u + n1];
        float2 x1 = in[5 * (u + 64) + n1];
        float2 x2 = in[5 * (u + 32) + n1];
        float2 x3 = in[5 * (u + 96) + n1];
        float2 w  = tw[5 * u];
        float2 w2 = cmul(w, w);
        float2 A0 = make_float2(x0.x + x1.x, x0.y + x1.y);
        float2 d0 = make_float2(x0.x - x1.x, x0.y - x1.y);
        float2 A1 = cmul(d0, w);
        float2 B0 = make_float2(x2.x + x3.x, x2.y + x3.y);
        float2 d1 = make_float2(x2.x - x3.x, x2.y - x3.y);
        float2 t1 = cmul(d1, w);
        float2 B1 = make_float2(t1.y, -t1.x);                // -i * t1
        const int bw = (n1 << 7) + 4 * u;
        float2 u2 = make_float2(A0.x - B0.x, A0.y - B0.y);
        float2 u3 = make_float2(A1.x - B1.x, A1.y - B1.y);
        B[SW1(bw)]     = make_float2(A0.x + B0.x, A0.y + B0.y);
        B[SW1(bw + 1)] = make_float2(A1.x + B1.x, A1.y + B1.y);
        B[SW1(bw + 2)] = cmul(u2, w2);
        B[SW1(bw + 3)] = cmul(u3, w2);
    }
    __syncthreads();

    // ---- stage 1 (s=4): B (SW1) -> A (SW2) ----
    {
        const int q  = u & 3;
        const int pp = u >> 2;
        const int br = (n1 << 7) + u;
        float2 x0 = B[SW1(br)];
        float2 x1 = B[SW1(br + 64)];
        float2 x2 = B[SW1(br + 32)];
        float2 x3 = B[SW1(br + 96)];
        float2 w  = tw[20 * pp];
        float2 w2 = cmul(w, w);
        float2 A0 = make_float2(x0.x + x1.x, x0.y + x1.y);
        float2 d0 = make_float2(x0.x - x1.x, x0.y - x1.y);
        float2 A1 = cmul(d0, w);
        float2 B0 = make_float2(x2.x + x3.x, x2.y + x3.y);
        float2 d1 = make_float2(x2.x - x3.x, x2.y - x3.y);
        float2 t1 = cmul(d1, w);
        float2 B1 = make_float2(t1.y, -t1.x);
        const int bw = (n1 << 7) + q + 16 * pp;
        float2 u2 = make_float2(A0.x - B0.x, A0.y - B0.y);
        float2 u3 = make_float2(A1.x - B1.x, A1.y - B1.y);
        A[SW2(bw)]      = make_float2(A0.x + B0.x, A0.y + B0.y);
        A[SW2(bw + 4)]  = make_float2(A1.x + B1.x, A1.y + B1.y);
        A[SW2(bw + 8)]  = cmul(u2, w2);
        A[SW2(bw + 12)] = cmul(u3, w2);
    }
    __syncthreads();

    // ---- stage 2 (s=16): A (SW2) -> B (SW1) ----
    {
        const int q  = u & 15;
        const int pp = u >> 4;
        const int br = (n1 << 7) + u;
        float2 x0 = A[SW2(br)];
        float2 x1 = A[SW2(br + 64)];
        float2 x2 = A[SW2(br + 32)];
        float2 x3 = A[SW2(br + 96)];
        float2 w  = tw[80 * pp];
        float2 w2 = cmul(w, w);
        float2 A0 = make_float2(x0.x + x1.x, x0.y + x1.y);
        float2 d0 = make_float2(x0.x - x1.x, x0.y - x1.y);
        float2 A1 = cmul(d0, w);
        float2 B0 = make_float2(x2.x + x3.x, x2.y + x3.y);
        float2 d1 = make_float2(x2.x - x3.x, x2.y - x3.y);
        float2 t1 = cmul(d1, w);
        float2 B1 = make_float2(t1.y, -t1.x);
        const int bw = (n1 << 7) + q + 64 * pp;
        float2 u2 = make_float2(A0.x - B0.x, A0.y - B0.y);
        float2 u3 = make_float2(A1.x - B1.x, A1.y - B1.y);
        B[SW1(bw)]      = make_float2(A0.x + B0.x, A0.y + B0.y);
        B[SW1(bw + 16)] = make_float2(A1.x + B1.x, A1.y + B1.y);
        B[SW1(bw + 32)] = cmul(u2, w2);
        B[SW1(bw + 48)] = cmul(u3, w2);
    }
    __syncthreads();

    // ---- fused radix-2 + twiddle + radix-5: B (SW1) -> out (natural) ----
    if (t < 256) {
        const int f5  = t >> 7;
        const int k2  = t & 127;
        const int k2l = k2 & 63;
        const float2* Bf = Wb + f5 * 640;
        float2* out = f5 ? out1 : out0;
        float2 w1 = tw[k2];
        float2 w2 = cmul(w1, w1);
        float2 w3 = cmul(w2, w1);
        float2 w4 = cmul(w2, w2);
        float2 g[5];
        #pragma unroll
        for (int j = 0; j < 5; j++) {
            float2 lo = Bf[SW1((j << 7) + k2l)];
            float2 hi = Bf[SW1((j << 7) + k2l + 64)];
            float2 pre = (k2 < 64)
                ? make_float2(lo.x + hi.x, lo.y + hi.y)
                : make_float2(lo.x - hi.x, lo.y - hi.y);
            g[j] = pre;
        }
        g[1] = cmul(g[1], w1);
        g[2] = cmul(g[2], w2);
        g[3] = cmul(g[3], w3);
        g[4] = cmul(g[4], w4);
        #pragma unroll
        for (int k1 = 0; k1 < 5; k1++) {
            float rx = 0.0f, ry = 0.0f;
            #pragma unroll
            for (int j = 0; j < 5; j++) {
                int id = (j * k1) % 5;
                rx += g[j].x * c5r[id] - g[j].y * c5i[id];
                ry += g[j].x * c5i[id] + g[j].y * c5r[id];
            }
            out[(k1 << 7) + k2] = make_float2(rx * outScale, ry * outScale);
        }
    }
}

// ---------------------------------------------------------------------------
// Row pass: fused coil-multiply + apodization + pad + ifftshift + row FFT.
// 2 rows per block; FFT output stored directly to global (coalesced).
// ---------------------------------------------------------------------------
__global__ void __launch_bounds__(320) row_fft_kernel(
        const float* __restrict__ img_r, const float* __restrict__ img_i,
        const float* __restrict__ sm_r,  const float* __restrict__ sm_i) {
    __shared__ float2 Wa[2 * GQ];
    __shared__ float2 Wb[2 * GQ];
    __shared__ float2 tw[GQ];
    const int coil = blockIdx.y;
    const int pair = blockIdx.x;
    const int t = threadIdx.x;

    for (int k = t; k < GQ; k += 320) tw[k] = g_tw[k];

    #pragma unroll
    for (int f = 0; f < 2; f++) {
        int rr = pair * 2 + f;
        int i  = (rr < 160) ? rr + 160 : rr - 160;
        float si = g_scale[i];
        #pragma unroll
        for (int kk = 0; kk < 2; kk++) {
            int cc = t + kk * 320;
            float2 v = make_float2(0.0f, 0.0f);
            if (cc < 160 || cc >= 480) {
                int j = (cc < 160) ? cc + 160 : cc - 480;
                float ir  = img_r[i * NIMG + j];
                float ii  = img_i[i * NIMG + j];
                float sr  = sm_r[((size_t)coil * NIMG + i) * NIMG + j];
                float sim = sm_i[((size_t)coil * NIMG + i) * NIMG + j];
                float sc  = si * g_scale[j];
                v.x = (ir * sr - ii * sim) * sc;
                v.y = (ir * sim + ii * sr) * sc;
            }
            Wa[f * GQ + cc] = v;                      // natural order
        }
    }
    __syncthreads();

    int rr0 = pair * 2, rr1 = pair * 2 + 1;
    int r0 = (rr0 < 160) ? rr0 : rr0 + 320;
    int r1 = (rr1 < 160) ? rr1 : rr1 + 320;
    float2* gout0 = g_gridA + ((size_t)coil * GQ + r0) * GQ;
    float2* gout1 = g_gridA + ((size_t)coil * GQ + r1) * GQ;
    fft640_v2(Wa, Wa + GQ, Wa, Wb, tw, t, gout0, gout1, 1.0f);
}

// ---------------------------------------------------------------------------
// Column pass: 4 columns per block staged through SMEM. FFT reads the
// staging buffer S directly (natural order) and writes back into S scaled;
// final copy to gridB is coalesced.
// ---------------------------------------------------------------------------
#define COLS_PER_BLK 4
#define SPITCH 642
__global__ void __launch_bounds__(320) col_fft_kernel() {
    __shared__ float2 S[COLS_PER_BLK * SPITCH];
    __shared__ float2 Wa[2 * GQ];
    __shared__ float2 Wb[2 * GQ];
    __shared__ float2 tw[GQ];
    const int coil = blockIdx.y;
    const int c0 = blockIdx.x * COLS_PER_BLK;
    const int t = threadIdx.x;
    const float2* gin = g_gridA + (size_t)coil * GQ * GQ;

    for (int k = t; k < GQ; k += 320) tw[k] = g_tw[k];

    // load 320 nonzero rows; zero the middle 320
    for (int idx = t; idx < 320 * COLS_PER_BLK; idx += 320) {
        int rr = idx >> 2, col = idx & 3;
        int row = (rr < 160) ? rr : rr + 320;
        S[col * SPITCH + row]      = gin[(size_t)row * GQ + c0 + col];
        S[col * SPITCH + 160 + rr] = make_float2(0.0f, 0.0f);
    }
    __syncthreads();

    #pragma unroll
    for (int ph = 0; ph < 2; ph++) {
        float2* s0 = S + (ph * 2) * SPITCH;
        float2* s1 = S + (ph * 2 + 1) * SPITCH;
        fft640_v2(s0, s1, Wa, Wb, tw, t, s0, s1, INV_G);
        __syncthreads();
    }

    float2* gout = g_gridB + (size_t)coil * GQ * GQ;
    for (int idx = t; idx < GQ * COLS_PER_BLK; idx += 320) {
        int row = idx >> 2, col = idx & 3;
        gout[(size_t)row * GQ + c0 + col] = S[col * SPITCH + row];
    }
}

// ---------------------------------------------------------------------------
// Transpose: g_gridB [coil][rc] -> g_gridC [rc][coil].
// Smem tile oriented [coil][rc] (pitch 258 -> float4-aligned rows):
//   load phase : contiguous float4 LDG + contiguous float4 STS (no conflicts)
//   store phase: 2x LDS.64 (sporadic 2-way) + contiguous float4 STG
// 256 rc per block, 256 threads, 6 items per thread per phase.
// ---------------------------------------------------------------------------
#define TRC 256
__global__ void __launch_bounds__(256) transpose_kernel() {
    __shared__ float2 T[NCOIL][TRC + 2];   // pitch 258 float2 = 2064B (16B-aligned)
    const int rc0 = blockIdx.x * TRC;
    const int t = threadIdx.x;

    // load: 12 coils x 128 float4 (= 256 rc) = 1536 float4 per block
    #pragma unroll
    for (int k = 0; k < 6; k++) {
        int idx = t + k * 256;
        int q = idx >> 7;                 // coil 0..11
        int i = idx & 127;                // float4 index -> rc pair (2i, 2i+1)
        const float4* src = (const float4*)(g_gridB + (size_t)q * (GQ * GQ) + rc0);
        float4 v = src[i];
        *(float4*)&T[q][2 * i] = v;       // contiguous, conflict-free
    }
    __syncthreads();

    // store: 256 rc x 6 coil-pairs = 1536 float4 per block (fully contiguous)
    float4* dst = (float4*)(g_gridC + (size_t)rc0 * NCOIL);
    #pragma unroll
    for (int k = 0; k < 6; k++) {
        int idx = t + k * 256;
        int rc = idx / 6;                 // 0..255
        int j  = idx - rc * 6;            // coil pair 0..5
        float2 a = T[2 * j][rc];
        float2 b = T[2 * j + 1][rc];
        dst[idx] = make_float4(a.x, a.y, b.x, b.y);
    }
}

// ---------------------------------------------------------------------------
// Interpolation: ONE WARP PER SAMPLE on coil-interleaved float2 grid.
// ---------------------------------------------------------------------------
#define WPB 8   // warps (samples) per block
__global__ void __launch_bounds__(32 * WPB) interp_kernel(const float* __restrict__ ktraj,
                                                          float* __restrict__ out) {
    __shared__ float2 s_part[WPB][72];
    __shared__ float2 s_out[NCOIL][WPB];
    const int warp = threadIdx.x >> 5;
    const int lane = threadIdx.x & 31;
    const int m = blockIdx.x * WPB + warp;

    float w = 0.0f;
    int   ki = 0;
    if (lane < 12) {
        int dim = lane >= 6 ? 1 : 0;
        int j   = lane - dim * 6;
        float om = ktraj[dim * MPTS + m];
        float tt = fmodf((om * 640.0f) / 6.2831855f, 640.0f);
        if (tt < 0.0f) tt += 640.0f;
        float base = floorf(tt);
        float k = base + (float)(j - 2);
        w = kbf(tt - k);
        ki = (int)k;
        if (ki < 0) ki += 640;
        else if (ki >= 640) ki -= 640;
    }

    const int e0 = lane, e1 = lane + 32, e2 = lane + 64;
    const int j0 = e0 / 12, j1 = e1 / 12;
    const int cc0 = e0 - j0 * 12, cc1 = e1 - j1 * 12, cc2 = e2 - 60;

    const unsigned FULL = 0xFFFFFFFFu;
    float wy0 = __shfl_sync(FULL, w, 6 + j0);
    float wy1 = __shfl_sync(FULL, w, 6 + j1);
    float wy2 = __shfl_sync(FULL, w, 11);
    int   iy0 = __shfl_sync(FULL, ki, 6 + j0);
    int   iy1 = __shfl_sync(FULL, ki, 6 + j1);
    int   iy2 = __shfl_sync(FULL, ki, 11);
    const int off0 = iy0 * NCOIL + cc0;
    const int off1 = iy1 * NCOIL + cc1;
    const int off2 = iy2 * NCOIL + cc2;
    const bool has2 = (lane < 8);

    float2 acc0 = make_float2(0.f, 0.f);
    float2 acc1 = make_float2(0.f, 0.f);
    float2 acc2 = make_float2(0.f, 0.f);

    #pragma unroll
    for (int i = 0; i < 6; i++) {
        float wx = __shfl_sync(FULL, w, i);
        int   ix = __shfl_sync(FULL, ki, i);
        const float2* __restrict__ rowp = g_gridC + (size_t)ix * (GQ * NCOIL);
        float2 v0 = __ldg(rowp + off0);
        float2 v1 = __ldg(rowp + off1);
        acc0.x += wx * v0.x; acc0.y += wx * v0.y;
        acc1.x += wx * v1.x; acc1.y += wx * v1.y;
        if (has2) {
            float2 v2 = __ldg(rowp + off2);
            acc2.x += wx * v2.x; acc2.y += wx * v2.y;
        }
    }

    s_part[warp][e0] = make_float2(wy0 * acc0.x, wy0 * acc0.y);
    s_part[warp][e1] = make_float2(wy1 * acc1.x, wy1 * acc1.y);
    if (has2) s_part[warp][e2] = make_float2(wy2 * acc2.x, wy2 * acc2.y);
    __syncwarp();

    if (lane < 12) {
        float rx = 0.f, ry = 0.f;
        #pragma unroll
        for (int j = 0; j < 6; j++) {
            float2 p = s_part[warp][j * 12 + lane];
            rx += p.x; ry += p.y;
        }
        s_out[lane][warp] = make_float2(rx, ry);
    }
    __syncthreads();

    if (threadIdx.x < NCOIL * WPB) {
        int c = threadIdx.x >> 3;
        int s = threadIdx.x & 7;
        ((float2*)out)[(size_t)c * MPTS + blockIdx.x * WPB + s] = s_out[c][s];
    }
}

// ---------------------------------------------------------------------------
extern "C" void kernel_launch(void* const* d_in, const int* in_sizes, int n_in,
                              void* d_out, int out_size) {
    const float* img_r = (const float*)d_in[0];
    const float* img_i = (const float*)d_in[1];
    const float* sm_r  = (const float*)d_in[2];
    const float* sm_i  = (const float*)d_in[3];
    const float* kt    = (const float*)d_in[4];
    float* out = (float*)d_out;

    apod_kernel<<<5, 128>>>();
    row_fft_kernel<<<dim3(160, NCOIL), 320>>>(img_r, img_i, sm_r, sm_i);
    col_fft_kernel<<<dim3(GQ / COLS_PER_BLK, NCOIL), 320>>>();
    transpose_kernel<<<(GQ * GQ) / TRC, 256>>>();
    interp_kernel<<<MPTS / WPB, 32 * WPB>>>(kt, out);
}

// round 13
// speedup vs baseline: 1.0198x; 1.0198x over previous
#include <cuda_runtime.h>
#include <cstdint>

#define GQ     640
#define NIMG   320
#define NCOIL  12
#define MPTS   102400
#define PI_F   3.14159265358979f
#define BETA_F 13.855101f      // pi * sqrt((6*1.5/2)^2 - 0.8)
#define INV_G  0.0015625f      // 1/640

// Per-boundary bank swizzles (float2 elements).
#define SW1(i) ((i) ^ (((i) >> 4) & 3))          // stage0->1 and stage2->r5 layouts
#define SW2(i) ((i) ^ ((((i) >> 4) & 3) << 2))   // stage1->2 layout

// Scratch (zero-initialized at module load).
// gridA stores ONLY the 320 nonzero (compacted) rows: index rr in [0,320).
__device__ float2 g_gridA[NCOIL * NIMG * GQ];               // [coil][rr][col], 19.6MB
__device__ float2 g_gridB[NCOIL * GQ * GQ];                 // [coil][row][col] after col FFT
__device__ __align__(16) float2 g_gridC[GQ * GQ * NCOIL];   // [row][col][coil]
__device__ float  g_scale[NIMG];
__device__ float2 g_tw[GQ];                                 // exp(-2*pi*i*k/640)

__constant__ float c5r[5] = {1.0f, 0.30901699f, -0.80901699f, -0.80901699f, 0.30901699f};
__constant__ float c5i[5] = {0.0f, -0.95105652f, -0.58778525f, 0.58778525f, 0.95105652f};

// ---------------------------------------------------------------------------
// Modified Bessel I0 (Abramowitz & Stegun, ~2e-7 rel error)
// ---------------------------------------------------------------------------
__device__ __forceinline__ float i0f_dev(float x) {
    if (x < 3.75f) {
        float t = x * (1.0f / 3.75f);
        t *= t;
        return 1.0f + t * (3.5156229f + t * (3.0899424f + t * (1.2067492f
             + t * (0.2659732f + t * (0.0360768f + t * 0.0045813f)))));
    } else {
        float t = 3.75f / x;
        float p = 0.39894228f + t * (0.00225319f * 0.0f + 0.01328592f + t * (0.00225319f + t * (-0.00157565f
                + t * (0.00916281f + t * (-0.02057706f + t * (0.02635537f
                + t * (-0.01647633f + t * 0.00392377f)))))));
        return expf(x) * rsqrtf(x) * p;
    }
}

// Kaiser-Bessel kernel, support |u| <= 3 (J=6)
__device__ __forceinline__ float kbf(float u) {
    float m = fabsf(u) * (1.0f / 3.0f);
    float a = 1.0f - m * m;
    a = a > 0.0f ? a : 0.0f;
    float v = i0f_dev(BETA_F * sqrtf(a)) * (1.0f / 6.0f);
    return (m <= 1.0f) ? v : 0.0f;
}

// ---------------------------------------------------------------------------
// Apodization scale (length 320) + twiddle table (length 640).
// grid = 5 blocks x 128 threads.
// ---------------------------------------------------------------------------
__global__ void apod_kernel() {
    int n = blockIdx.x * 128 + threadIdx.x;
    if (n < NIMG) {
        float acc = 0.0f;
        #pragma unroll
        for (int j = -6; j <= 6; j++) {
            float kv = kbf((float)j);
            acc += kv * cosf(2.0f * PI_F * (float)j * ((float)n - 160.0f) * (1.0f / 640.0f));
        }
        g_scale[n] = 1.0f / acc;
    }
    if (n < GQ) {
        float sn, cs;
        sincospif(-(float)n * (1.0f / 320.0f), &sn, &cs);   // -2*pi*n/640
        g_tw[n] = make_float2(cs, sn);
    }
}

__device__ __forceinline__ float2 cmul(float2 a, float2 b) {
    return make_float2(a.x * b.x - a.y * b.y, a.x * b.y + a.y * b.x);
}

// ---------------------------------------------------------------------------
// TWO 640-point forward FFTs per call (radix-4 Stockham x3 + fused radix-2 +
// radix-5, per-boundary swizzles). blockDim.x == 320.
// ---------------------------------------------------------------------------
__device__ void fft640_v2(const float2* in0, const float2* in1,
                          float2* Wa, float2* Wb, const float2* tw, int t,
                          float2* out0, float2* out1, float outScale) {
    const int f  = (t >= 160) ? 1 : 0;
    const int lt = t - 160 * f;
    const int n1 = lt >> 5;
    const int u  = lt & 31;
    const float2* in = f ? in1 : in0;
    float2* A = Wa + f * 640;
    float2* B = Wb + f * 640;

    // ---- stage 0 (s=1): natural in -> B (SW1) ----
    {
        float2 x0 = in[5 * u + n1];
        float2 x1 = in[5 * (u + 64) + n1];
        float2 x2 = in[5 * (u + 32) + n1];
        float2 x3 = in[5 * (u + 96) + n1];
        float2 w  = tw[5 * u];
        float2 w2 = cmul(w, w);
        float2 A0 = make_float2(x0.x + x1.x, x0.y + x1.y);
        float2 d0 = make_float2(x0.x - x1.x, x0.y - x1.y);
        float2 A1 = cmul(d0, w);
        float2 B0 = make_float2(x2.x + x3.x, x2.y + x3.y);
        float2 d1 = make_float2(x2.x - x3.x, x2.y - x3.y);
        float2 t1 = cmul(d1, w);
        float2 B1 = make_float2(t1.y, -t1.x);                // -i * t1
        const int bw = (n1 << 7) + 4 * u;
        float2 u2 = make_float2(A0.x - B0.x, A0.y - B0.y);
        float2 u3 = make_float2(A1.x - B1.x, A1.y - B1.y);
        B[SW1(bw)]     = make_float2(A0.x + B0.x, A0.y + B0.y);
        B[SW1(bw + 1)] = make_float2(A1.x + B1.x, A1.y + B1.y);
        B[SW1(bw + 2)] = cmul(u2, w2);
        B[SW1(bw + 3)] = cmul(u3, w2);
    }
    __syncthreads();

    // ---- stage 1 (s=4): B (SW1) -> A (SW2) ----
    {
        const int q  = u & 3;
        const int pp = u >> 2;
        const int br = (n1 << 7) + u;
        float2 x0 = B[SW1(br)];
        float2 x1 = B[SW1(br + 64)];
        float2 x2 = B[SW1(br + 32)];
        float2 x3 = B[SW1(br + 96)];
        float2 w  = tw[20 * pp];
        float2 w2 = cmul(w, w);
        float2 A0 = make_float2(x0.x + x1.x, x0.y + x1.y);
        float2 d0 = make_float2(x0.x - x1.x, x0.y - x1.y);
        float2 A1 = cmul(d0, w);
        float2 B0 = make_float2(x2.x + x3.x, x2.y + x3.y);
        float2 d1 = make_float2(x2.x - x3.x, x2.y - x3.y);
        float2 t1 = cmul(d1, w);
        float2 B1 = make_float2(t1.y, -t1.x);
        const int bw = (n1 << 7) + q + 16 * pp;
        float2 u2 = make_float2(A0.x - B0.x, A0.y - B0.y);
        float2 u3 = make_float2(A1.x - B1.x, A1.y - B1.y);
        A[SW2(bw)]      = make_float2(A0.x + B0.x, A0.y + B0.y);
        A[SW2(bw + 4)]  = make_float2(A1.x + B1.x, A1.y + B1.y);
        A[SW2(bw + 8)]  = cmul(u2, w2);
        A[SW2(bw + 12)] = cmul(u3, w2);
    }
    __syncthreads();

    // ---- stage 2 (s=16): A (SW2) -> B (SW1) ----
    {
        const int q  = u & 15;
        const int pp = u >> 4;
        const int br = (n1 << 7) + u;
        float2 x0 = A[SW2(br)];
        float2 x1 = A[SW2(br + 64)];
        float2 x2 = A[SW2(br + 32)];
        float2 x3 = A[SW2(br + 96)];
        float2 w  = tw[80 * pp];
        float2 w2 = cmul(w, w);
        float2 A0 = make_float2(x0.x + x1.x, x0.y + x1.y);
        float2 d0 = make_float2(x0.x - x1.x, x0.y - x1.y);
        float2 A1 = cmul(d0, w);
        float2 B0 = make_float2(x2.x + x3.x, x2.y + x3.y);
        float2 d1 = make_float2(x2.x - x3.x, x2.y - x3.y);
        float2 t1 = cmul(d1, w);
        float2 B1 = make_float2(t1.y, -t1.x);
        const int bw = (n1 << 7) + q + 64 * pp;
        float2 u2 = make_float2(A0.x - B0.x, A0.y - B0.y);
        float2 u3 = make_float2(A1.x - B1.x, A1.y - B1.y);
        B[SW1(bw)]      = make_float2(A0.x + B0.x, A0.y + B0.y);
        B[SW1(bw + 16)] = make_float2(A1.x + B1.x, A1.y + B1.y);
        B[SW1(bw + 32)] = cmul(u2, w2);
        B[SW1(bw + 48)] = cmul(u3, w2);
    }
    __syncthreads();

    // ---- fused radix-2 + twiddle + radix-5: B (SW1) -> out (natural) ----
    if (t < 256) {
        const int f5  = t >> 7;
        const int k2  = t & 127;
        const int k2l = k2 & 63;
        const float2* Bf = Wb + f5 * 640;
        float2* out = f5 ? out1 : out0;
        float2 w1 = tw[k2];
        float2 w2 = cmul(w1, w1);
        float2 w3 = cmul(w2, w1);
        float2 w4 = cmul(w2, w2);
        float2 g[5];
        #pragma unroll
        for (int j = 0; j < 5; j++) {
            float2 lo = Bf[SW1((j << 7) + k2l)];
            float2 hi = Bf[SW1((j << 7) + k2l + 64)];
            float2 pre = (k2 < 64)
                ? make_float2(lo.x + hi.x, lo.y + hi.y)
                : make_float2(lo.x - hi.x, lo.y - hi.y);
            g[j] = pre;
        }
        g[1] = cmul(g[1], w1);
        g[2] = cmul(g[2], w2);
        g[3] = cmul(g[3], w3);
        g[4] = cmul(g[4], w4);
        #pragma unroll
        for (int k1 = 0; k1 < 5; k1++) {
            float rx = 0.0f, ry = 0.0f;
            #pragma unroll
            for (int j = 0; j < 5; j++) {
                int id = (j * k1) % 5;
                rx += g[j].x * c5r[id] - g[j].y * c5i[id];
                ry += g[j].x * c5i[id] + g[j].y * c5r[id];
            }
            out[(k1 << 7) + k2] = make_float2(rx * outScale, ry * outScale);
        }
    }
}

// ---------------------------------------------------------------------------
// Row pass: fused coil-multiply + apodization + pad + ifftshift + row FFT.
// 2 rows per block; output stored directly to COMPACTED gridA (row index rr).
// ---------------------------------------------------------------------------
__global__ void __launch_bounds__(320) row_fft_kernel(
        const float* __restrict__ img_r, const float* __restrict__ img_i,
        const float* __restrict__ sm_r,  const float* __restrict__ sm_i) {
    __shared__ float2 Wa[2 * GQ];
    __shared__ float2 Wb[2 * GQ];
    __shared__ float2 tw[GQ];
    const int coil = blockIdx.y;
    const int pair = blockIdx.x;
    const int t = threadIdx.x;

    for (int k = t; k < GQ; k += 320) tw[k] = g_tw[k];

    #pragma unroll
    for (int f = 0; f < 2; f++) {
        int rr = pair * 2 + f;
        int i  = (rr < 160) ? rr + 160 : rr - 160;
        float si = g_scale[i];
        #pragma unroll
        for (int kk = 0; kk < 2; kk++) {
            int cc = t + kk * 320;
            float2 v = make_float2(0.0f, 0.0f);
            if (cc < 160 || cc >= 480) {
                int j = (cc < 160) ? cc + 160 : cc - 480;
                float ir  = img_r[i * NIMG + j];
                float ii  = img_i[i * NIMG + j];
                float sr  = sm_r[((size_t)coil * NIMG + i) * NIMG + j];
                float sim = sm_i[((size_t)coil * NIMG + i) * NIMG + j];
                float sc  = si * g_scale[j];
                v.x = (ir * sr - ii * sim) * sc;
                v.y = (ir * sim + ii * sr) * sc;
            }
            Wa[f * GQ + cc] = v;                      // natural order
        }
    }
    __syncthreads();

    int rr0 = pair * 2, rr1 = pair * 2 + 1;
    float2* gout0 = g_gridA + ((size_t)coil * NIMG + rr0) * GQ;   // compacted
    float2* gout1 = g_gridA + ((size_t)coil * NIMG + rr1) * GQ;
    fft640_v2(Wa, Wa + GQ, Wa, Wb, tw, t, gout0, gout1, 1.0f);
}

// ---------------------------------------------------------------------------
// Column pass: 4 columns per block staged through SMEM. Reads compacted
// gridA rows (rr index), places them at shifted positions, zeros the middle.
// ---------------------------------------------------------------------------
#define COLS_PER_BLK 4
#define SPITCH 642
__global__ void __launch_bounds__(320) col_fft_kernel() {
    __shared__ float2 S[COLS_PER_BLK * SPITCH];
    __shared__ float2 Wa[2 * GQ];
    __shared__ float2 Wb[2 * GQ];
    __shared__ float2 tw[GQ];
    const int coil = blockIdx.y;
    const int c0 = blockIdx.x * COLS_PER_BLK;
    const int t = threadIdx.x;
    const float2* gin = g_gridA + (size_t)coil * NIMG * GQ;   // compacted rows

    for (int k = t; k < GQ; k += 320) tw[k] = g_tw[k];

    // load 320 compacted rows into their shifted positions; zero the middle
    for (int idx = t; idx < 320 * COLS_PER_BLK; idx += 320) {
        int rr = idx >> 2, col = idx & 3;
        int row = (rr < 160) ? rr : rr + 320;        // shifted grid row
        S[col * SPITCH + row]      = gin[(size_t)rr * GQ + c0 + col];
        S[col * SPITCH + 160 + rr] = make_float2(0.0f, 0.0f);
    }
    __syncthreads();

    #pragma unroll
    for (int ph = 0; ph < 2; ph++) {
        float2* s0 = S + (ph * 2) * SPITCH;
        float2* s1 = S + (ph * 2 + 1) * SPITCH;
        fft640_v2(s0, s1, Wa, Wb, tw, t, s0, s1, INV_G);
        __syncthreads();
    }

    float2* gout = g_gridB + (size_t)coil * GQ * GQ;
    for (int idx = t; idx < GQ * COLS_PER_BLK; idx += 320) {
        int row = idx >> 2, col = idx & 3;
        gout[(size_t)row * GQ + c0 + col] = S[col * SPITCH + row];
    }
}

// ---------------------------------------------------------------------------
// Transpose: g_gridB [coil][rc] -> g_gridC [rc][coil], float4 both sides
// (exact R10 version: 128 rc per block, 256 threads).
// ---------------------------------------------------------------------------
#define TRC2 128
__global__ void __launch_bounds__(256) transpose_kernel() {
    __shared__ float2 T[TRC2][NCOIL + 1];
    const int rc0 = blockIdx.x * TRC2;
    const int t = threadIdx.x;

    #pragma unroll
    for (int k = 0; k < 3; k++) {
        int idx = t + k * 256;
        int q = idx >> 6;
        int i = idx & 63;
        const float4* src = (const float4*)(g_gridB + (size_t)q * (GQ * GQ) + rc0);
        float4 v = src[i];
        T[2 * i][q]     = make_float2(v.x, v.y);
        T[2 * i + 1][q] = make_float2(v.z, v.w);
    }
    __syncthreads();

    float4* dst = (float4*)(g_gridC + (size_t)rc0 * NCOIL);
    #pragma unroll
    for (int k = 0; k < 3; k++) {
        int idx = t + k * 256;
        int rc = idx / 6;
        int j  = idx - rc * 6;
        float2 a = T[rc][2 * j];
        float2 b = T[rc][2 * j + 1];
        dst[idx] = make_float4(a.x, a.y, b.x, b.y);
    }
}

// ---------------------------------------------------------------------------
// Interpolation: ONE WARP PER SAMPLE on coil-interleaved float2 grid.
// ---------------------------------------------------------------------------
#define WPB 8   // warps (samples) per block
__global__ void __launch_bounds__(32 * WPB) interp_kernel(const float* __restrict__ ktraj,
                                                          float* __restrict__ out) {
    __shared__ float2 s_part[WPB][72];
    __shared__ float2 s_out[NCOIL][WPB];
    const int warp = threadIdx.x >> 5;
    const int lane = threadIdx.x & 31;
    const int m = blockIdx.x * WPB + warp;

    float w = 0.0f;
    int   ki = 0;
    if (lane < 12) {
        int dim = lane >= 6 ? 1 : 0;
        int j   = lane - dim * 6;
        float om = ktraj[dim * MPTS + m];
        float tt = fmodf((om * 640.0f) / 6.2831855f, 640.0f);
        if (tt < 0.0f) tt += 640.0f;
        float base = floorf(tt);
        float k = base + (float)(j - 2);
        w = kbf(tt - k);
        ki = (int)k;
        if (ki < 0) ki += 640;
        else if (ki >= 640) ki -= 640;
    }

    const int e0 = lane, e1 = lane + 32, e2 = lane + 64;
    const int j0 = e0 / 12, j1 = e1 / 12;
    const int cc0 = e0 - j0 * 12, cc1 = e1 - j1 * 12, cc2 = e2 - 60;

    const unsigned FULL = 0xFFFFFFFFu;
    float wy0 = __shfl_sync(FULL, w, 6 + j0);
    float wy1 = __shfl_sync(FULL, w, 6 + j1);
    float wy2 = __shfl_sync(FULL, w, 11);
    int   iy0 = __shfl_sync(FULL, ki, 6 + j0);
    int   iy1 = __shfl_sync(FULL, ki, 6 + j1);
    int   iy2 = __shfl_sync(FULL, ki, 11);
    const int off0 = iy0 * NCOIL + cc0;
    const int off1 = iy1 * NCOIL + cc1;
    const int off2 = iy2 * NCOIL + cc2;
    const bool has2 = (lane < 8);

    float2 acc0 = make_float2(0.f, 0.f);
    float2 acc1 = make_float2(0.f, 0.f);
    float2 acc2 = make_float2(0.f, 0.f);

    #pragma unroll
    for (int i = 0; i < 6; i++) {
        float wx = __shfl_sync(FULL, w, i);
        int   ix = __shfl_sync(FULL, ki, i);
        const float2* __restrict__ rowp = g_gridC + (size_t)ix * (GQ * NCOIL);
        float2 v0 = __ldg(rowp + off0);
        float2 v1 = __ldg(rowp + off1);
        acc0.x += wx * v0.x; acc0.y += wx * v0.y;
        acc1.x += wx * v1.x; acc1.y += wx * v1.y;
        if (has2) {
            float2 v2 = __ldg(rowp + off2);
            acc2.x += wx * v2.x; acc2.y += wx * v2.y;
        }
    }

    s_part[warp][e0] = make_float2(wy0 * acc0.x, wy0 * acc0.y);
    s_part[warp][e1] = make_float2(wy1 * acc1.x, wy1 * acc1.y);
    if (has2) s_part[warp][e2] = make_float2(wy2 * acc2.x, wy2 * acc2.y);
    __syncwarp();

    if (lane < 12) {
        float rx = 0.f, ry = 0.f;
        #pragma unroll
        for (int j = 0; j < 6; j++) {
            float2 p = s_part[warp][j * 12 + lane];
            rx += p.x; ry += p.y;
        }
        s_out[lane][warp] = make_float2(rx, ry);
    }
    __syncthreads();

    if (threadIdx.x < NCOIL * WPB) {
        int c = threadIdx.x >> 3;
        int s = threadIdx.x & 7;
        ((float2*)out)[(size_t)c * MPTS + blockIdx.x * WPB + s] = s_out[c][s];
    }
}

// ---------------------------------------------------------------------------
extern "C" void kernel_launch(void* const* d_in, const int* in_sizes, int n_in,
                              void* d_out, int out_size) {
    const float* img_r = (const float*)d_in[0];
    const float* img_i = (const float*)d_in[1];
    const float* sm_r  = (const float*)d_in[2];
    const float* sm_i  = (const float*)d_in[3];
    const float* kt    = (const float*)d_in[4];
    float* out = (float*)d_out;

    apod_kernel<<<5, 128>>>();
    row_fft_kernel<<<dim3(160, NCOIL), 320>>>(img_r, img_i, sm_r, sm_i);
    col_fft_kernel<<<dim3(GQ / COLS_PER_BLK, NCOIL), 320>>>();
    transpose_kernel<<<(GQ * GQ) / TRC2, 256>>>();
    interp_kernel<<<MPTS / WPB, 32 * WPB>>>(kt, out);
}

// round 14
// speedup vs baseline: 1.1127x; 1.0912x over previous
#include <cuda_runtime.h>
#include <cstdint>

#define GQ     640
#define NIMG   320
#define NCOIL  12
#define MPTS   102400
#define PI_F   3.14159265358979f
#define BETA_F 13.855101f      // pi * sqrt((6*1.5/2)^2 - 0.8)
#define INV_G  0.0015625f      // 1/640

// Per-boundary bank swizzles (float2 elements).
#define SW1(i) ((i) ^ (((i) >> 4) & 3))          // stage0->1 and stage2->r5 layouts
#define SW2(i) ((i) ^ ((((i) >> 4) & 3) << 2))   // stage1->2 layout

// Scratch (zero-initialized at module load).
// gridA stores ONLY the 320 nonzero (compacted) rows: index rr in [0,320).
__device__ float2 g_gridA[NCOIL * NIMG * GQ];               // [coil][rr][col], 19.6MB
__device__ __align__(16) float2 g_gridC[GQ * GQ * NCOIL];   // [row][col][coil], 39MB
__device__ float  g_scale[NIMG];
__device__ float2 g_tw[GQ];                                 // exp(-2*pi*i*k/640)

__constant__ float c5r[5] = {1.0f, 0.30901699f, -0.80901699f, -0.80901699f, 0.30901699f};
__constant__ float c5i[5] = {0.0f, -0.95105652f, -0.58778525f, 0.58778525f, 0.95105652f};

// ---------------------------------------------------------------------------
// Modified Bessel I0 (Abramowitz & Stegun, ~2e-7 rel error)
// ---------------------------------------------------------------------------
__device__ __forceinline__ float i0f_dev(float x) {
    if (x < 3.75f) {
        float t = x * (1.0f / 3.75f);
        t *= t;
        return 1.0f + t * (3.5156229f + t * (3.0899424f + t * (1.2067492f
             + t * (0.2659732f + t * (0.0360768f + t * 0.0045813f)))));
    } else {
        float t = 3.75f / x;
        float p = 0.39894228f + t * (0.01328592f + t * (0.00225319f + t * (-0.00157565f
                + t * (0.00916281f + t * (-0.02057706f + t * (0.02635537f
                + t * (-0.01647633f + t * 0.00392377f)))))));
        return expf(x) * rsqrtf(x) * p;
    }
}

// Kaiser-Bessel kernel, support |u| <= 3 (J=6)
__device__ __forceinline__ float kbf(float u) {
    float m = fabsf(u) * (1.0f / 3.0f);
    float a = 1.0f - m * m;
    a = a > 0.0f ? a : 0.0f;
    float v = i0f_dev(BETA_F * sqrtf(a)) * (1.0f / 6.0f);
    return (m <= 1.0f) ? v : 0.0f;
}

// ---------------------------------------------------------------------------
// Apodization scale (length 320) + twiddle table (length 640).
// grid = 5 blocks x 128 threads.
// ---------------------------------------------------------------------------
__global__ void apod_kernel() {
    int n = blockIdx.x * 128 + threadIdx.x;
    if (n < NIMG) {
        float acc = 0.0f;
        #pragma unroll
        for (int j = -6; j <= 6; j++) {
            float kv = kbf((float)j);
            acc += kv * cosf(2.0f * PI_F * (float)j * ((float)n - 160.0f) * (1.0f / 640.0f));
        }
        g_scale[n] = 1.0f / acc;
    }
    if (n < GQ) {
        float sn, cs;
        sincospif(-(float)n * (1.0f / 320.0f), &sn, &cs);   // -2*pi*n/640
        g_tw[n] = make_float2(cs, sn);
    }
}

__device__ __forceinline__ float2 cmul(float2 a, float2 b) {
    return make_float2(a.x * b.x - a.y * b.y, a.x * b.y + a.y * b.x);
}

// ---------------------------------------------------------------------------
// TWO 640-point forward FFTs per call (radix-4 Stockham x3 + fused radix-2 +
// radix-5, per-boundary swizzles). blockDim.x == 320.
// NOTE: no trailing __syncthreads(); caller adds one if buffers are reused.
// ---------------------------------------------------------------------------
__device__ void fft640_v2(const float2* in0, const float2* in1,
                          float2* Wa, float2* Wb, const float2* tw, int t,
                          float2* out0, float2* out1, float outScale) {
    const int f  = (t >= 160) ? 1 : 0;
    const int lt = t - 160 * f;
    const int n1 = lt >> 5;
    const int u  = lt & 31;
    const float2* in = f ? in1 : in0;
    float2* A = Wa + f * 640;
    float2* B = Wb + f * 640;

    // ---- stage 0 (s=1): natural in -> B (SW1) ----
    {
        float2 x0 = in[5 * u + n1];
        float2 x1 = in[5 * (u + 64) + n1];
        float2 x2 = in[5 * (u + 32) + n1];
        float2 x3 = in[5 * (u + 96) + n1];
        float2 w  = tw[5 * u];
        float2 w2 = cmul(w, w);
        float2 A0 = make_float2(x0.x + x1.x, x0.y + x1.y);
        float2 d0 = make_float2(x0.x - x1.x, x0.y - x1.y);
        float2 A1 = cmul(d0, w);
        float2 B0 = make_float2(x2.x + x3.x, x2.y + x3.y);
        float2 d1 = make_float2(x2.x - x3.x, x2.y - x3.y);
        float2 t1 = cmul(d1, w);
        float2 B1 = make_float2(t1.y, -t1.x);                // -i * t1
        const int bw = (n1 << 7) + 4 * u;
        float2 u2 = make_float2(A0.x - B0.x, A0.y - B0.y);
        float2 u3 = make_float2(A1.x - B1.x, A1.y - B1.y);
        B[SW1(bw)]     = make_float2(A0.x + B0.x, A0.y + B0.y);
        B[SW1(bw + 1)] = make_float2(A1.x + B1.x, A1.y + B1.y);
        B[SW1(bw + 2)] = cmul(u2, w2);
        B[SW1(bw + 3)] = cmul(u3, w2);
    }
    __syncthreads();

    // ---- stage 1 (s=4): B (SW1) -> A (SW2) ----
    {
        const int q  = u & 3;
        const int pp = u >> 2;
        const int br = (n1 << 7) + u;
        float2 x0 = B[SW1(br)];
        float2 x1 = B[SW1(br + 64)];
        float2 x2 = B[SW1(br + 32)];
        float2 x3 = B[SW1(br + 96)];
        float2 w  = tw[20 * pp];
        float2 w2 = cmul(w, w);
        float2 A0 = make_float2(x0.x + x1.x, x0.y + x1.y);
        float2 d0 = make_float2(x0.x - x1.x, x0.y - x1.y);
        float2 A1 = cmul(d0, w);
        float2 B0 = make_float2(x2.x + x3.x, x2.y + x3.y);
        float2 d1 = make_float2(x2.x - x3.x, x2.y - x3.y);
        float2 t1 = cmul(d1, w);
        float2 B1 = make_float2(t1.y, -t1.x);
        const int bw = (n1 << 7) + q + 16 * pp;
        float2 u2 = make_float2(A0.x - B0.x, A0.y - B0.y);
        float2 u3 = make_float2(A1.x - B1.x, A1.y - B1.y);
        A[SW2(bw)]      = make_float2(A0.x + B0.x, A0.y + B0.y);
        A[SW2(bw + 4)]  = make_float2(A1.x + B1.x, A1.y + B1.y);
        A[SW2(bw + 8)]  = cmul(u2, w2);
        A[SW2(bw + 12)] = cmul(u3, w2);
    }
    __syncthreads();

    // ---- stage 2 (s=16): A (SW2) -> B (SW1) ----
    {
        const int q  = u & 15;
        const int pp = u >> 4;
        const int br = (n1 << 7) + u;
        float2 x0 = A[SW2(br)];
        float2 x1 = A[SW2(br + 64)];
        float2 x2 = A[SW2(br + 32)];
        float2 x3 = A[SW2(br + 96)];
        float2 w  = tw[80 * pp];
        float2 w2 = cmul(w, w);
        float2 A0 = make_float2(x0.x + x1.x, x0.y + x1.y);
        float2 d0 = make_float2(x0.x - x1.x, x0.y - x1.y);
        float2 A1 = cmul(d0, w);
        float2 B0 = make_float2(x2.x + x3.x, x2.y + x3.y);
        float2 d1 = make_float2(x2.x - x3.x, x2.y - x3.y);
        float2 t1 = cmul(d1, w);
        float2 B1 = make_float2(t1.y, -t1.x);
        const int bw = (n1 << 7) + q + 64 * pp;
        float2 u2 = make_float2(A0.x - B0.x, A0.y - B0.y);
        float2 u3 = make_float2(A1.x - B1.x, A1.y - B1.y);
        B[SW1(bw)]      = make_float2(A0.x + B0.x, A0.y + B0.y);
        B[SW1(bw + 16)] = make_float2(A1.x + B1.x, A1.y + B1.y);
        B[SW1(bw + 32)] = cmul(u2, w2);
        B[SW1(bw + 48)] = cmul(u3, w2);
    }
    __syncthreads();

    // ---- fused radix-2 + twiddle + radix-5: B (SW1) -> out (natural) ----
    if (t < 256) {
        const int f5  = t >> 7;
        const int k2  = t & 127;
        const int k2l = k2 & 63;
        const float2* Bf = Wb + f5 * 640;
        float2* out = f5 ? out1 : out0;
        float2 w1 = tw[k2];
        float2 w2 = cmul(w1, w1);
        float2 w3 = cmul(w2, w1);
        float2 w4 = cmul(w2, w2);
        float2 g[5];
        #pragma unroll
        for (int j = 0; j < 5; j++) {
            float2 lo = Bf[SW1((j << 7) + k2l)];
            float2 hi = Bf[SW1((j << 7) + k2l + 64)];
            float2 pre = (k2 < 64)
                ? make_float2(lo.x + hi.x, lo.y + hi.y)
                : make_float2(lo.x - hi.x, lo.y - hi.y);
            g[j] = pre;
        }
        g[1] = cmul(g[1], w1);
        g[2] = cmul(g[2], w2);
        g[3] = cmul(g[3], w3);
        g[4] = cmul(g[4], w4);
        #pragma unroll
        for (int k1 = 0; k1 < 5; k1++) {
            float rx = 0.0f, ry = 0.0f;
            #pragma unroll
            for (int j = 0; j < 5; j++) {
                int id = (j * k1) % 5;
                rx += g[j].x * c5r[id] - g[j].y * c5i[id];
                ry += g[j].x * c5i[id] + g[j].y * c5r[id];
            }
            out[(k1 << 7) + k2] = make_float2(rx * outScale, ry * outScale);
        }
    }
}

// ---------------------------------------------------------------------------
// Row pass: fused coil-multiply + apodization + pad + ifftshift + row FFT.
// 2 rows per block; output stored directly to COMPACTED gridA (row index rr).
// ---------------------------------------------------------------------------
__global__ void __launch_bounds__(320) row_fft_kernel(
        const float* __restrict__ img_r, const float* __restrict__ img_i,
        const float* __restrict__ sm_r,  const float* __restrict__ sm_i) {
    __shared__ float2 Wa[2 * GQ];
    __shared__ float2 Wb[2 * GQ];
    __shared__ float2 tw[GQ];
    const int coil = blockIdx.y;
    const int pair = blockIdx.x;
    const int t = threadIdx.x;

    for (int k = t; k < GQ; k += 320) tw[k] = g_tw[k];

    #pragma unroll
    for (int f = 0; f < 2; f++) {
        int rr = pair * 2 + f;
        int i  = (rr < 160) ? rr + 160 : rr - 160;
        float si = g_scale[i];
        #pragma unroll
        for (int kk = 0; kk < 2; kk++) {
            int cc = t + kk * 320;
            float2 v = make_float2(0.0f, 0.0f);
            if (cc < 160 || cc >= 480) {
                int j = (cc < 160) ? cc + 160 : cc - 480;
                float ir  = img_r[i * NIMG + j];
                float ii  = img_i[i * NIMG + j];
                float sr  = sm_r[((size_t)coil * NIMG + i) * NIMG + j];
                float sim = sm_i[((size_t)coil * NIMG + i) * NIMG + j];
                float sc  = si * g_scale[j];
                v.x = (ir * sr - ii * sim) * sc;
                v.y = (ir * sim + ii * sr) * sc;
            }
            Wa[f * GQ + cc] = v;                      // natural order
        }
    }
    __syncthreads();

    int rr0 = pair * 2, rr1 = pair * 2 + 1;
    float2* gout0 = g_gridA + ((size_t)coil * NIMG + rr0) * GQ;   // compacted
    float2* gout1 = g_gridA + ((size_t)coil * NIMG + rr1) * GQ;
    fft640_v2(Wa, Wa + GQ, Wa, Wb, tw, t, gout0, gout1, 1.0f);
}

// ---------------------------------------------------------------------------
// Column pass, fused with coil interleave: block = 2 columns x 2 coils.
// Reads compacted gridA (streaming hint), runs 4 column FFTs, then writes
// gridC DIRECTLY as float4 = adjacent coil pair (16B-aligned): no separate
// transpose kernel, no gridB.
// grid = (320 col-pairs, 6 coil-pairs), block = 320.
// ---------------------------------------------------------------------------
#define SPITCH 642
__global__ void __launch_bounds__(320) col_fft_kernel() {
    __shared__ float2 S[4 * SPITCH];        // [coil(2)][col(2)][row 642]
    __shared__ float2 Wa[2 * GQ];
    __shared__ float2 Wb[2 * GQ];
    __shared__ float2 tw[GQ];
    const int bp = blockIdx.y;              // coil pair 0..5
    const int q0 = bp * 2;                  // first coil of the pair
    const int c0 = blockIdx.x * 2;          // first column
    const int t = threadIdx.x;

    for (int k = t; k < GQ; k += 320) tw[k] = g_tw[k];

    // load 320 compacted rows for 2 coils x 2 cols; zero the middle 320
    for (int idx = t; idx < 320 * 4; idx += 320) {
        int rr   = idx >> 2;
        int slot = idx & 3;                 // cl = slot>>1, col = slot&1
        int cl   = slot >> 1;
        int col  = slot & 1;
        int row  = (rr < 160) ? rr : rr + 320;          // shifted grid row
        const float2* gin = g_gridA + ((size_t)(q0 + cl) * NIMG + rr) * GQ;
        S[slot * SPITCH + row]      = __ldcs(gin + c0 + col);
        S[slot * SPITCH + 160 + rr] = make_float2(0.0f, 0.0f);
    }
    __syncthreads();

    // FFT both columns of each coil (in-place in S, scaled by 1/640)
    #pragma unroll
    for (int cl = 0; cl < 2; cl++) {
        float2* s0 = S + (cl * 2 + 0) * SPITCH;
        float2* s1 = S + (cl * 2 + 1) * SPITCH;
        fft640_v2(s0, s1, Wa, Wb, tw, t, s0, s1, INV_G);
        __syncthreads();
    }

    // direct interleaved store: float4 = (coil q0, coil q0+1) for one rc
    float4* dst = (float4*)g_gridC;         // float4 index = rc*6 + bp
    for (int idx = t; idx < 640 * 2; idx += 320) {
        int row = idx >> 1;
        int col = idx & 1;
        float2 a = S[(0 * 2 + col) * SPITCH + row];     // coil q0
        float2 b = S[(1 * 2 + col) * SPITCH + row];     // coil q0+1
        size_t rc = (size_t)row * GQ + c0 + col;
        dst[rc * 6 + bp] = make_float4(a.x, a.y, b.x, b.y);
    }
}

// ---------------------------------------------------------------------------
// Interpolation: ONE WARP PER SAMPLE on coil-interleaved float2 grid.
// ---------------------------------------------------------------------------
#define WPB 8   // warps (samples) per block
__global__ void __launch_bounds__(32 * WPB) interp_kernel(const float* __restrict__ ktraj,
                                                          float* __restrict__ out) {
    __shared__ float2 s_part[WPB][72];
    __shared__ float2 s_out[NCOIL][WPB];
    const int warp = threadIdx.x >> 5;
    const int lane = threadIdx.x & 31;
    const int m = blockIdx.x * WPB + warp;

    float w = 0.0f;
    int   ki = 0;
    if (lane < 12) {
        int dim = lane >= 6 ? 1 : 0;
        int j   = lane - dim * 6;
        float om = ktraj[dim * MPTS + m];
        float tt = fmodf((om * 640.0f) / 6.2831855f, 640.0f);
        if (tt < 0.0f) tt += 640.0f;
        float base = floorf(tt);
        float k = base + (float)(j - 2);
        w = kbf(tt - k);
        ki = (int)k;
        if (ki < 0) ki += 640;
        else if (ki >= 640) ki -= 640;
    }

    const int e0 = lane, e1 = lane + 32, e2 = lane + 64;
    const int j0 = e0 / 12, j1 = e1 / 12;
    const int cc0 = e0 - j0 * 12, cc1 = e1 - j1 * 12, cc2 = e2 - 60;

    const unsigned FULL = 0xFFFFFFFFu;
    float wy0 = __shfl_sync(FULL, w, 6 + j0);
    float wy1 = __shfl_sync(FULL, w, 6 + j1);
    float wy2 = __shfl_sync(FULL, w, 11);
    int   iy0 = __shfl_sync(FULL, ki, 6 + j0);
    int   iy1 = __shfl_sync(FULL, ki, 6 + j1);
    int   iy2 = __shfl_sync(FULL, ki, 11);
    const int off0 = iy0 * NCOIL + cc0;
    const int off1 = iy1 * NCOIL + cc1;
    const int off2 = iy2 * NCOIL + cc2;
    const bool has2 = (lane < 8);

    float2 acc0 = make_float2(0.f, 0.f);
    float2 acc1 = make_float2(0.f, 0.f);
    float2 acc2 = make_float2(0.f, 0.f);

    #pragma unroll
    for (int i = 0; i < 6; i++) {
        float wx = __shfl_sync(FULL, w, i);
        int   ix = __shfl_sync(FULL, ki, i);
        const float2* __restrict__ rowp = g_gridC + (size_t)ix * (GQ * NCOIL);
        float2 v0 = __ldg(rowp + off0);
        float2 v1 = __ldg(rowp + off1);
        acc0.x += wx * v0.x; acc0.y += wx * v0.y;
        acc1.x += wx * v1.x; acc1.y += wx * v1.y;
        if (has2) {
            float2 v2 = __ldg(rowp + off2);
            acc2.x += wx * v2.x; acc2.y += wx * v2.y;
        }
    }

    s_part[warp][e0] = make_float2(wy0 * acc0.x, wy0 * acc0.y);
    s_part[warp][e1] = make_float2(wy1 * acc1.x, wy1 * acc1.y);
    if (has2) s_part[warp][e2] = make_float2(wy2 * acc2.x, wy2 * acc2.y);
    __syncwarp();

    if (lane < 12) {
        float rx = 0.f, ry = 0.f;
        #pragma unroll
        for (int j = 0; j < 6; j++) {
            float2 p = s_part[warp][j * 12 + lane];
            rx += p.x; ry += p.y;
        }
        s_out[lane][warp] = make_float2(rx, ry);
    }
    __syncthreads();

    if (threadIdx.x < NCOIL * WPB) {
        int c = threadIdx.x >> 3;
        int s = threadIdx.x & 7;
        ((float2*)out)[(size_t)c * MPTS + blockIdx.x * WPB + s] = s_out[c][s];
    }
}

// ---------------------------------------------------------------------------
extern "C" void kernel_launch(void* const* d_in, const int* in_sizes, int n_in,
                              void* d_out, int out_size) {
    const float* img_r = (const float*)d_in[0];
    const float* img_i = (const float*)d_in[1];
    const float* sm_r  = (const float*)d_in[2];
    const float* sm_i  = (const float*)d_in[3];
    const float* kt    = (const float*)d_in[4];
    float* out = (float*)d_out;

    apod_kernel<<<5, 128>>>();
    row_fft_kernel<<<dim3(160, NCOIL), 320>>>(img_r, img_i, sm_r, sm_i);
    col_fft_kernel<<<dim3(320, 6), 320>>>();
    interp_kernel<<<MPTS / WPB, 32 * WPB>>>(kt, out);
}

// round 16
// speedup vs baseline: 1.1344x; 1.0195x over previous
#include <cuda_runtime.h>
#include <cstdint>

#define GQ     640
#define NIMG   320
#define NCOIL  12
#define MPTS   102400
#define PI_F   3.14159265358979f
#define BETA_F 13.855101f      // pi * sqrt((6*1.5/2)^2 - 0.8)
#define INV_G  0.0015625f      // 1/640

// Per-boundary bank swizzles (float2 elements).
#define SW1(i) ((i) ^ (((i) >> 4) & 3))          // stage0->1 and stage2->r5 layouts
#define SW2(i) ((i) ^ ((((i) >> 4) & 3) << 2))   // stage1->2 layout

// Scratch (zero-initialized at module load).
// gridA stores ONLY the 320 nonzero (compacted) rows: index rr in [0,320).
__device__ float2 g_gridA[NCOIL * NIMG * GQ];               // [coil][rr][col], 19.6MB
__device__ __align__(16) float2 g_gridC[GQ * GQ * NCOIL];   // [row][col][coil], 39MB
__device__ float  g_scale[NIMG];
__device__ float2 g_tw[GQ];                                 // exp(-2*pi*i*k/640)

__constant__ float c5r[5] = {1.0f, 0.30901699f, -0.80901699f, -0.80901699f, 0.30901699f};
__constant__ float c5i[5] = {0.0f, -0.95105652f, -0.58778525f, 0.58778525f, 0.95105652f};

// ---------------------------------------------------------------------------
// Modified Bessel I0 (Abramowitz & Stegun, ~2e-7 rel error)
// ---------------------------------------------------------------------------
__device__ __forceinline__ float i0f_dev(float x) {
    if (x < 3.75f) {
        float t = x * (1.0f / 3.75f);
        t *= t;
        return 1.0f + t * (3.5156229f + t * (3.0899424f + t * (1.2067492f
             + t * (0.2659732f + t * (0.0360768f + t * 0.0045813f)))));
    } else {
        float t = 3.75f / x;
        float p = 0.39894228f + t * (0.01328592f + t * (0.00225319f + t * (-0.00157565f
                + t * (0.00916281f + t * (-0.02057706f + t * (0.02635537f
                + t * (-0.01647633f + t * 0.00392377f)))))));
        return expf(x) * rsqrtf(x) * p;
    }
}

// Kaiser-Bessel kernel, support |u| <= 3 (J=6)
__device__ __forceinline__ float kbf(float u) {
    float m = fabsf(u) * (1.0f / 3.0f);
    float a = 1.0f - m * m;
    a = a > 0.0f ? a : 0.0f;
    float v = i0f_dev(BETA_F * sqrtf(a)) * (1.0f / 6.0f);
    return (m <= 1.0f) ? v : 0.0f;
}

// ---------------------------------------------------------------------------
// Apodization scale (length 320) + twiddle table (length 640).
// grid = 5 blocks x 128 threads.
// ---------------------------------------------------------------------------
__global__ void apod_kernel() {
    int n = blockIdx.x * 128 + threadIdx.x;
    if (n < NIMG) {
        float acc = 0.0f;
        #pragma unroll
        for (int j = -6; j <= 6; j++) {
            float kv = kbf((float)j);
            acc += kv * cosf(2.0f * PI_F * (float)j * ((float)n - 160.0f) * (1.0f / 640.0f));
        }
        g_scale[n] = 1.0f / acc;
    }
    if (n < GQ) {
        float sn, cs;
        sincospif(-(float)n * (1.0f / 320.0f), &sn, &cs);   // -2*pi*n/640
        g_tw[n] = make_float2(cs, sn);
    }
}

__device__ __forceinline__ float2 cmul(float2 a, float2 b) {
    return make_float2(a.x * b.x - a.y * b.y, a.x * b.y + a.y * b.x);
}

// ---------------------------------------------------------------------------
// TWO 640-point forward FFTs per call, with PRUNED COMPACT INPUT:
// the natural-order input has x[160..479] == 0; callers provide only the
// 320 nonzero values as Cin[i] = x[i < 160 ? i : i + 320].
// Stage 0 exploits x1 = x2 = 0:
//   A0 = x0, A1 = x0*w, B0 = x3, B1 = -i*(0 - x3)*w = +i*(x3*w).
// 640 = 5*128; 128 = three composed radix-4 Stockham stages + radix-2
// (fused into the radix-5 combine). Per-boundary swizzles. blockDim.x == 320.
// in0/in1: compact 320-entry arrays (only read in stage 0, before any
// smem write in this call). Outputs out0/out1: natural order, x outScale.
// NOTE: no trailing __syncthreads(); caller adds one if buffers are reused.
// ---------------------------------------------------------------------------
__device__ void fft640_pruned(const float2* in0, const float2* in1,
                              float2* Wa, float2* Wb, const float2* tw, int t,
                              float2* out0, float2* out1, float outScale) {
    const int f  = (t >= 160) ? 1 : 0;
    const int lt = t - 160 * f;
    const int n1 = lt >> 5;
    const int u  = lt & 31;
    const float2* in = f ? in1 : in0;
    float2* A = Wa + f * 640;
    float2* B = Wb + f * 640;

    // ---- stage 0 (s=1), pruned: x1 = x2 = 0 ----
    {
        float2 x0 = in[5 * u + n1];          // natural idx 5u+n1 < 160
        float2 x3 = in[5 * u + 160 + n1];    // natural idx 5u+480+n1 -> compact -320
        float2 w  = tw[5 * u];
        float2 w2 = cmul(w, w);
        float2 A0 = x0;
        float2 A1 = cmul(x0, w);
        float2 B0 = x3;
        float2 t1 = cmul(x3, w);
        float2 B1 = make_float2(-t1.y, t1.x);                // +i * t1  (x2 == 0!)
        const int bw = (n1 << 7) + 4 * u;
        float2 u2 = make_float2(A0.x - B0.x, A0.y - B0.y);
        float2 u3 = make_float2(A1.x - B1.x, A1.y - B1.y);
        B[SW1(bw)]     = make_float2(A0.x + B0.x, A0.y + B0.y);
        B[SW1(bw + 1)] = make_float2(A1.x + B1.x, A1.y + B1.y);
        B[SW1(bw + 2)] = cmul(u2, w2);
        B[SW1(bw + 3)] = cmul(u3, w2);
    }
    __syncthreads();

    // ---- stage 1 (s=4): B (SW1) -> A (SW2) ----
    {
        const int q  = u & 3;
        const int pp = u >> 2;
        const int br = (n1 << 7) + u;
        float2 x0 = B[SW1(br)];
        float2 x1 = B[SW1(br + 64)];
        float2 x2 = B[SW1(br + 32)];
        float2 x3 = B[SW1(br + 96)];
        float2 w  = tw[20 * pp];
        float2 w2 = cmul(w, w);
        float2 A0 = make_float2(x0.x + x1.x, x0.y + x1.y);
        float2 d0 = make_float2(x0.x - x1.x, x0.y - x1.y);
        float2 A1 = cmul(d0, w);
        float2 B0 = make_float2(x2.x + x3.x, x2.y + x3.y);
        float2 d1 = make_float2(x2.x - x3.x, x2.y - x3.y);
        float2 t1 = cmul(d1, w);
        float2 B1 = make_float2(t1.y, -t1.x);
        const int bw = (n1 << 7) + q + 16 * pp;
        float2 u2 = make_float2(A0.x - B0.x, A0.y - B0.y);
        float2 u3 = make_float2(A1.x - B1.x, A1.y - B1.y);
        A[SW2(bw)]      = make_float2(A0.x + B0.x, A0.y + B0.y);
        A[SW2(bw + 4)]  = make_float2(A1.x + B1.x, A1.y + B1.y);
        A[SW2(bw + 8)]  = cmul(u2, w2);
        A[SW2(bw + 12)] = cmul(u3, w2);
    }
    __syncthreads();

    // ---- stage 2 (s=16): A (SW2) -> B (SW1) ----
    {
        const int q  = u & 15;
        const int pp = u >> 4;
        const int br = (n1 << 7) + u;
        float2 x0 = A[SW2(br)];
        float2 x1 = A[SW2(br + 64)];
        float2 x2 = A[SW2(br + 32)];
        float2 x3 = A[SW2(br + 96)];
        float2 w  = tw[80 * pp];
        float2 w2 = cmul(w, w);
        float2 A0 = make_float2(x0.x + x1.x, x0.y + x1.y);
        float2 d0 = make_float2(x0.x - x1.x, x0.y - x1.y);
        float2 A1 = cmul(d0, w);
        float2 B0 = make_float2(x2.x + x3.x, x2.y + x3.y);
        float2 d1 = make_float2(x2.x - x3.x, x2.y - x3.y);
        float2 t1 = cmul(d1, w);
        float2 B1 = make_float2(t1.y, -t1.x);
        const int bw = (n1 << 7) + q + 64 * pp;
        float2 u2 = make_float2(A0.x - B0.x, A0.y - B0.y);
        float2 u3 = make_float2(A1.x - B1.x, A1.y - B1.y);
        B[SW1(bw)]      = make_float2(A0.x + B0.x, A0.y + B0.y);
        B[SW1(bw + 16)] = make_float2(A1.x + B1.x, A1.y + B1.y);
        B[SW1(bw + 32)] = cmul(u2, w2);
        B[SW1(bw + 48)] = cmul(u3, w2);
    }
    __syncthreads();

    // ---- fused radix-2 + twiddle + radix-5: B (SW1) -> out (natural) ----
    if (t < 256) {
        const int f5  = t >> 7;
        const int k2  = t & 127;
        const int k2l = k2 & 63;
        const float2* Bf = Wb + f5 * 640;
        float2* out = f5 ? out1 : out0;
        float2 w1 = tw[k2];
        float2 w2 = cmul(w1, w1);
        float2 w3 = cmul(w2, w1);
        float2 w4 = cmul(w2, w2);
        float2 g[5];
        #pragma unroll
        for (int j = 0; j < 5; j++) {
            float2 lo = Bf[SW1((j << 7) + k2l)];
            float2 hi = Bf[SW1((j << 7) + k2l + 64)];
            float2 pre = (k2 < 64)
                ? make_float2(lo.x + hi.x, lo.y + hi.y)
                : make_float2(lo.x - hi.x, lo.y - hi.y);
            g[j] = pre;
        }
        g[1] = cmul(g[1], w1);
        g[2] = cmul(g[2], w2);
        g[3] = cmul(g[3], w3);
        g[4] = cmul(g[4], w4);
        #pragma unroll
        for (int k1 = 0; k1 < 5; k1++) {
            float rx = 0.0f, ry = 0.0f;
            #pragma unroll
            for (int j = 0; j < 5; j++) {
                int id = (j * k1) % 5;
                rx += g[j].x * c5r[id] - g[j].y * c5i[id];
                ry += g[j].x * c5i[id] + g[j].y * c5r[id];
            }
            out[(k1 << 7) + k2] = make_float2(rx * outScale, ry * outScale);
        }
    }
}

// ---------------------------------------------------------------------------
// Row pass: fused coil-multiply + apodization + pad + ifftshift + row FFT.
// 2 rows per block. Fill writes ONLY the 320 nonzero values (compact form)
// into Wa; stage 0 consumes them before Wa is overwritten by stage 1.
// Output stored directly to COMPACTED gridA (row index rr).
// ---------------------------------------------------------------------------
__global__ void __launch_bounds__(320) row_fft_kernel(
        const float* __restrict__ img_r, const float* __restrict__ img_i,
        const float* __restrict__ sm_r,  const float* __restrict__ sm_i) {
    __shared__ float2 Wa[2 * GQ];
    __shared__ float2 Wb[2 * GQ];
    __shared__ float2 tw[GQ];
    const int coil = blockIdx.y;
    const int pair = blockIdx.x;
    const int t = threadIdx.x;

    for (int k = t; k < GQ; k += 320) tw[k] = g_tw[k];

    // compact fill: thread t -> compact index t; source image col
    // j = t<160 ? t+160 : t-160  (natural cc = t<160 ? t : t+320)
    #pragma unroll
    for (int f = 0; f < 2; f++) {
        int rr = pair * 2 + f;
        int i  = (rr < 160) ? rr + 160 : rr - 160;     // source image row
        float si = g_scale[i];
        int j = (t < 160) ? t + 160 : t - 160;         // source image col
        float ir  = img_r[i * NIMG + j];
        float ii  = img_i[i * NIMG + j];
        float sr  = sm_r[((size_t)coil * NIMG + i) * NIMG + j];
        float sim = sm_i[((size_t)coil * NIMG + i) * NIMG + j];
        float sc  = si * g_scale[j];
        Wa[f * GQ + t] = make_float2((ir * sr - ii * sim) * sc,
                                     (ir * sim + ii * sr) * sc);
    }
    __syncthreads();

    int rr0 = pair * 2, rr1 = pair * 2 + 1;
    float2* gout0 = g_gridA + ((size_t)coil * NIMG + rr0) * GQ;   // compacted
    float2* gout1 = g_gridA + ((size_t)coil * NIMG + rr1) * GQ;
    fft640_pruned(Wa, Wa + GQ, Wa, Wb, tw, t, gout0, gout1, 1.0f);
}

// ---------------------------------------------------------------------------
// Column pass, fused with coil interleave: block = 2 columns x 2 coils.
// Stages only the 320 compacted gridA rows (no zero materialization);
// the pruned FFT regenerates the zero-padded spectrum. Writes gridC
// DIRECTLY as float4 = adjacent coil pair. grid = (320, 6), block = 320.
// ---------------------------------------------------------------------------
#define SPITCH 642
__global__ void __launch_bounds__(320) col_fft_kernel() {
    __shared__ float2 S[4 * SPITCH];        // [coil(2)][col(2)]: compact in, natural out
    __shared__ float2 Wa[2 * GQ];
    __shared__ float2 Wb[2 * GQ];
    __shared__ float2 tw[GQ];
    const int bp = blockIdx.y;              // coil pair 0..5
    const int q0 = bp * 2;                  // first coil of the pair
    const int c0 = blockIdx.x * 2;          // first column
    const int t = threadIdx.x;

    for (int k = t; k < GQ; k += 320) tw[k] = g_tw[k];

    // compact fill: 320 rows x (2 coils x 2 cols); gridA rr order IS the
    // compact FFT-input order (Cin[i] = x[i<160 ? i : i+320]).
    for (int idx = t; idx < 320 * 4; idx += 320) {
        int rr   = idx >> 2;
        int slot = idx & 3;                 // cl = slot>>1, col = slot&1
        int cl   = slot >> 1;
        int col  = slot & 1;
        const float2* gin = g_gridA + ((size_t)(q0 + cl) * NIMG + rr) * GQ;
        S[slot * SPITCH + rr] = __ldcs(gin + c0 + col);
    }
    __syncthreads();

    // FFT both columns of each coil; compact input in S slot, natural-order
    // output written back into the same slot (input consumed in stage 0).
    #pragma unroll
    for (int cl = 0; cl < 2; cl++) {
        float2* s0 = S + (cl * 2 + 0) * SPITCH;
        float2* s1 = S + (cl * 2 + 1) * SPITCH;
        fft640_pruned(s0, s1, Wa, Wb, tw, t, s0, s1, INV_G);
        __syncthreads();
    }

    // direct interleaved store: float4 = (coil q0, coil q0+1) for one rc
    float4* dst = (float4*)g_gridC;         // float4 index = rc*6 + bp
    for (int idx = t; idx < 640 * 2; idx += 320) {
        int row = idx >> 1;
        int col = idx & 1;
        float2 a = S[(0 * 2 + col) * SPITCH + row];     // coil q0
        float2 b = S[(1 * 2 + col) * SPITCH + row];     // coil q0+1
        size_t rc = (size_t)row * GQ + c0 + col;
        dst[rc * 6 + bp] = make_float4(a.x, a.y, b.x, b.y);
    }
}

// ---------------------------------------------------------------------------
// Interpolation: ONE WARP PER SAMPLE on coil-interleaved float2 grid.
// ---------------------------------------------------------------------------
#define WPB 8   // warps (samples) per block
__global__ void __launch_bounds__(32 * WPB) interp_kernel(const float* __restrict__ ktraj,
                                                          float* __restrict__ out) {
    __shared__ float2 s_part[WPB][72];
    __shared__ float2 s_out[NCOIL][WPB];
    const int warp = threadIdx.x >> 5;
    const int lane = threadIdx.x & 31;
    const int m = blockIdx.x * WPB + warp;

    float w = 0.0f;
    int   ki = 0;
    if (lane < 12) {
        int dim = lane >= 6 ? 1 : 0;
        int j   = lane - dim * 6;
        float om = ktraj[dim * MPTS + m];
        float tt = fmodf((om * 640.0f) / 6.2831855f, 640.0f);
        if (tt < 0.0f) tt += 640.0f;
        float base = floorf(tt);
        float k = base + (float)(j - 2);
        w = kbf(tt - k);
        ki = (int)k;
        if (ki < 0) ki += 640;
        else if (ki >= 640) ki -= 640;
    }

    const int e0 = lane, e1 = lane + 32, e2 = lane + 64;
    const int j0 = e0 / 12, j1 = e1 / 12;
    const int cc0 = e0 - j0 * 12, cc1 = e1 - j1 * 12, cc2 = e2 - 60;

    const unsigned FULL = 0xFFFFFFFFu;
    float wy0 = __shfl_sync(FULL, w, 6 + j0);
    float wy1 = __shfl_sync(FULL, w, 6 + j1);
    float wy2 = __shfl_sync(FULL, w, 11);
    int   iy0 = __shfl_sync(FULL, ki, 6 + j0);
    int   iy1 = __shfl_sync(FULL, ki, 6 + j1);
    int   iy2 = __shfl_sync(FULL, ki, 11);
    const int off0 = iy0 * NCOIL + cc0;
    const int off1 = iy1 * NCOIL + cc1;
    const int off2 = iy2 * NCOIL + cc2;
    const bool has2 = (lane < 8);

    float2 acc0 = make_float2(0.f, 0.f);
    float2 acc1 = make_float2(0.f, 0.f);
    float2 acc2 = make_float2(0.f, 0.f);

    #pragma unroll
    for (int i = 0; i < 6; i++) {
        float wx = __shfl_sync(FULL, w, i);
        int   ix = __shfl_sync(FULL, ki, i);
        const float2* __restrict__ rowp = g_gridC + (size_t)ix * (GQ * NCOIL);
        float2 v0 = __ldg(rowp + off0);
        float2 v1 = __ldg(rowp + off1);
        acc0.x += wx * v0.x; acc0.y += wx * v0.y;
        acc1.x += wx * v1.x; acc1.y += wx * v1.y;
        if (has2) {
            float2 v2 = __ldg(rowp + off2);
            acc2.x += wx * v2.x; acc2.y += wx * v2.y;
        }
    }

    s_part[warp][e0] = make_float2(wy0 * acc0.x, wy0 * acc0.y);
    s_part[warp][e1] = make_float2(wy1 * acc1.x, wy1 * acc1.y);
    if (has2) s_part[warp][e2] = make_float2(wy2 * acc2.x, wy2 * acc2.y);
    __syncwarp();

    if (lane < 12) {
        float rx = 0.f, ry = 0.f;
        #pragma unroll
        for (int j = 0; j < 6; j++) {
            float2 p = s_part[warp][j * 12 + lane];
            rx += p.x; ry += p.y;
        }
        s_out[lane][warp] = make_float2(rx, ry);
    }
    __syncthreads();

    if (threadIdx.x < NCOIL * WPB) {
        int c = threadIdx.x >> 3;
        int s = threadIdx.x & 7;
        ((float2*)out)[(size_t)c * MPTS + blockIdx.x * WPB + s] = s_out[c][s];
    }
}

// ---------------------------------------------------------------------------
extern "C" void kernel_launch(void* const* d_in, const int* in_sizes, int n_in,
                              void* d_out, int out_size) {
    const float* img_r = (const float*)d_in[0];
    const float* img_i = (const float*)d_in[1];
    const float* sm_r  = (const float*)d_in[2];
    const float* sm_i  = (const float*)d_in[3];
    const float* kt    = (const float*)d_in[4];
    float* out = (float*)d_out;

    apod_kernel<<<5, 128>>>();
    row_fft_kernel<<<dim3(160, NCOIL), 320>>>(img_r, img_i, sm_r, sm_i);
    col_fft_kernel<<<dim3(320, 6), 320>>>();
    interp_kernel<<<MPTS / WPB, 32 * WPB>>>(kt, out);
}